// round 10
// baseline (speedup 1.0000x reference)
#include <cuda_runtime.h>
#include <cuda_bf16.h>
#include <cstdint>

// Problem shape (fixed for this problem instance)
#define NVARS  100000
#define NFACT  50000
#define NEDGES 1000000
#define DIM    128

// Scratch (no cudaMalloc allowed) — device globals
__device__ float g_P[(size_t)NVARS * DIM];     // variables @ W1
__device__ float g_Q[(size_t)NFACT * DIM];     // factors  @ W2
__device__ float g_aggr[(size_t)NVARS * DIM];  // segment_sum of messages

// ---------------------------------------------------------------------------
// f32x2 helpers (Blackwell packed fp32 pipe — 2x FFMA lane rate)
// ---------------------------------------------------------------------------
__device__ __forceinline__ void ffma2(unsigned long long& acc,
                                      unsigned long long a,
                                      unsigned long long b) {
    asm("fma.rn.f32x2 %0, %1, %2, %0;" : "+l"(acc) : "l"(a), "l"(b));
}
__device__ __forceinline__ unsigned long long pack2(float x) {
    unsigned long long r;
    asm("mov.b64 %0, {%1, %1};" : "=l"(r) : "f"(x));
    return r;
}
__device__ __forceinline__ float2 unpack2(unsigned long long v) {
    float2 r;
    asm("mov.b64 {%0, %1}, %2;" : "=f"(r.x), "=f"(r.y) : "l"(v));
    return r;
}

// ---------------------------------------------------------------------------
// Tiled GEMM: C[M,128] = sum_h A_h[M,128] @ W[h*128 : (h+1)*128, 0:128]
// Optional epilogue: C = resid + relu(acc + bias)
//
// Block: 256 threads = 8 warps, computes 128 rows x 128 cols.
// Warp w: rows [w*16, w*16+16). Lane: cgrp = lane&15 -> cols [cgrp*8, +8),
//         rgrp = lane>>4 -> rows [w*16 + rgrp*8, +8).
// Thread: 8 rows x 8 cols held as 32 f32x2 accumulators (pairs over cols).
// Dynamic smem: sW[128*128] + sA[128*128] = 128 KB.
// ---------------------------------------------------------------------------
__global__ __launch_bounds__(256) void gemm128_kernel(
    const float* __restrict__ A0, const float* __restrict__ A1,
    const float* __restrict__ W, int nhalves,
    const float* __restrict__ bias, const float* __restrict__ resid,
    float* __restrict__ C, int M)
{
    extern __shared__ float smem[];
    float* sW = smem;              // 128*128 floats
    float* sA = smem + 128 * 128;  // 128*128 floats

    const int tid  = threadIdx.x;
    const int lane = tid & 31;
    const int warp = tid >> 5;
    const int cgrp = lane & 15;
    const int rgrp = lane >> 4;
    const int row0 = blockIdx.x * 128;
    const int rows = (M - row0 < 128) ? (M - row0) : 128;
    const int rbase = warp * 16 + rgrp * 8;  // thread's first row within block
    const int c0 = cgrp * 8;                 // thread's first col

    unsigned long long acc[8][4];
#pragma unroll
    for (int r = 0; r < 8; r++)
#pragma unroll
        for (int j = 0; j < 4; j++) acc[r][j] = 0ull;

    for (int h = 0; h < nhalves; h++) {
        const float* Wh = W + (size_t)h * 128 * 128;
        const float* Ah = (h == 0) ? A0 : A1;
        __syncthreads();
        // Stage W half: 4096 float4, coalesced
#pragma unroll 4
        for (int i = tid; i < (128 * 128) / 4; i += 256)
            reinterpret_cast<float4*>(sW)[i] =
                reinterpret_cast<const float4*>(Wh)[i];
        // Stage A tile: rows*32 float4
        const float4* Asrc = reinterpret_cast<const float4*>(Ah + (size_t)row0 * 128);
        for (int i = tid; i < rows * 32; i += 256)
            reinterpret_cast<float4*>(sA)[i] = Asrc[i];
        __syncthreads();

#pragma unroll 4
        for (int k = 0; k < 128; k++) {
            const float* wrow = sW + k * 128 + c0;
            ulonglong2 wA = *reinterpret_cast<const ulonglong2*>(wrow);      // cols c0..c0+3
            ulonglong2 wB = *reinterpret_cast<const ulonglong2*>(wrow + 4);  // cols c0+4..c0+7
            const float* acol = sA + rbase * 128 + k;
#pragma unroll
            for (int r = 0; r < 8; r++) {
                unsigned long long a2 = pack2(acol[r * 128]);
                ffma2(acc[r][0], a2, wA.x);
                ffma2(acc[r][1], a2, wA.y);
                ffma2(acc[r][2], a2, wB.x);
                ffma2(acc[r][3], a2, wB.y);
            }
        }
    }

    // Epilogue
    float bv[8];
    if (bias) {
        float4 b0 = *reinterpret_cast<const float4*>(bias + c0);
        float4 b1 = *reinterpret_cast<const float4*>(bias + c0 + 4);
        bv[0] = b0.x; bv[1] = b0.y; bv[2] = b0.z; bv[3] = b0.w;
        bv[4] = b1.x; bv[5] = b1.y; bv[6] = b1.z; bv[7] = b1.w;
    }
#pragma unroll
    for (int r = 0; r < 8; r++) {
        int row = row0 + rbase + r;
        if (row < M) {
            float o[8];
            float2 u;
            u = unpack2(acc[r][0]); o[0] = u.x; o[1] = u.y;
            u = unpack2(acc[r][1]); o[2] = u.x; o[3] = u.y;
            u = unpack2(acc[r][2]); o[4] = u.x; o[5] = u.y;
            u = unpack2(acc[r][3]); o[6] = u.x; o[7] = u.y;
            if (bias) {
#pragma unroll
                for (int j = 0; j < 8; j++) o[j] = fmaxf(o[j] + bv[j], 0.f);
            }
            if (resid) {
                const float* rp = resid + (size_t)row * 128 + c0;
                float4 r0 = *reinterpret_cast<const float4*>(rp);
                float4 r1 = *reinterpret_cast<const float4*>(rp + 4);
                o[0] += r0.x; o[1] += r0.y; o[2] += r0.z; o[3] += r0.w;
                o[4] += r1.x; o[5] += r1.y; o[6] += r1.z; o[7] += r1.w;
            }
            float* cp = C + (size_t)row * 128 + c0;
            *reinterpret_cast<float4*>(cp)     = make_float4(o[0], o[1], o[2], o[3]);
            *reinterpret_cast<float4*>(cp + 4) = make_float4(o[4], o[5], o[6], o[7]);
        }
    }
}

// ---------------------------------------------------------------------------
// Edge kernel: one warp per edge.
//   m = relu(P[v] + Q[f] + b_msg);  aggr[v] += m  (vectorized L2 reduction)
// ---------------------------------------------------------------------------
__global__ __launch_bounds__(256) void edge_kernel(
    const int* __restrict__ v_to_f, const int* __restrict__ f_to_v,
    const float* __restrict__ bmsg, int E)
{
    const int gwarp = (blockIdx.x * blockDim.x + threadIdx.x) >> 5;
    if (gwarp >= E) return;
    const int lane = threadIdx.x & 31;
    const int v = __ldg(v_to_f + gwarp);
    const int f = __ldg(f_to_v + gwarp);
    const int c = lane * 4;

    float4 p = *reinterpret_cast<const float4*>(g_P + (size_t)v * 128 + c);
    float4 q = *reinterpret_cast<const float4*>(g_Q + (size_t)f * 128 + c);
    float4 b = __ldg(reinterpret_cast<const float4*>(bmsg + c));

    float m0 = fmaxf(p.x + q.x + b.x, 0.f);
    float m1 = fmaxf(p.y + q.y + b.y, 0.f);
    float m2 = fmaxf(p.z + q.z + b.z, 0.f);
    float m3 = fmaxf(p.w + q.w + b.w, 0.f);

    float* dst = g_aggr + (size_t)v * 128 + c;
    asm volatile("red.global.add.v4.f32 [%0], {%1, %2, %3, %4};"
                 :: "l"(dst), "f"(m0), "f"(m1), "f"(m2), "f"(m3)
                 : "memory");
}

// ---------------------------------------------------------------------------
// Launch
// ---------------------------------------------------------------------------
extern "C" void kernel_launch(void* const* d_in, const int* in_sizes, int n_in,
                              void* d_out, int out_size)
{
    const float* variables = (const float*)d_in[0];
    const float* factors   = (const float*)d_in[1];
    const int*   v_to_f    = (const int*)d_in[2];
    const int*   f_to_v    = (const int*)d_in[3];
    // d_in[4] = edge_attr: unused (reference zeroes it)
    const float* W_msg     = (const float*)d_in[5];  // [257,128]
    const float* b_msg     = (const float*)d_in[6];  // [128]
    const float* W_comb    = (const float*)d_in[7];  // [256,128]
    const float* b_comb    = (const float*)d_in[8];  // [128]
    float* out = (float*)d_out;

    const int n_vars = in_sizes[0] / DIM;
    const int n_fact = in_sizes[1] / DIM;
    const int n_edge = in_sizes[2];

    float *pP = nullptr, *pQ = nullptr, *pAggr = nullptr;
    cudaGetSymbolAddress((void**)&pP, g_P);
    cudaGetSymbolAddress((void**)&pQ, g_Q);
    cudaGetSymbolAddress((void**)&pAggr, g_aggr);

    const size_t smem_bytes = (size_t)2 * 128 * 128 * sizeof(float);  // 128 KB
    cudaFuncSetAttribute(gemm128_kernel,
                         cudaFuncAttributeMaxDynamicSharedMemorySize,
                         (int)smem_bytes);

    cudaStream_t s = 0;

    // 1) zero aggregation buffer
    cudaMemsetAsync(pAggr, 0, (size_t)n_vars * DIM * sizeof(float), s);

    // 2) P = variables @ W_msg[0:128]
    gemm128_kernel<<<(n_vars + 127) / 128, 256, smem_bytes, s>>>(
        variables, nullptr, W_msg, 1, nullptr, nullptr, pP, n_vars);

    // 3) Q = factors @ W_msg[128:256]
    gemm128_kernel<<<(n_fact + 127) / 128, 256, smem_bytes, s>>>(
        factors, nullptr, W_msg + 128 * 128, 1, nullptr, nullptr, pQ, n_fact);

    // 4) per-edge relu + scatter-add
    int edge_blocks = (n_edge + 7) / 8;  // 8 warps (edges) per 256-thread block
    edge_kernel<<<edge_blocks, 256, 0, s>>>(v_to_f, f_to_v, b_msg, n_edge);

    // 5) out = variables + relu(variables@Wc1 + aggr@Wc2 + b_comb)
    gemm128_kernel<<<(n_vars + 127) / 128, 256, smem_bytes, s>>>(
        variables, pAggr, W_comb, 2, b_comb, variables, out, n_vars);
}

// round 11
// speedup vs baseline: 1.0010x; 1.0010x over previous
#include <cuda_runtime.h>
#include <cuda_bf16.h>
#include <cstdint>

// Problem shape (fixed for this problem instance)
#define NVARS  100000
#define NFACT  50000
#define NEDGES 1000000
#define DIM    128

// Scratch (no cudaMalloc allowed) — device globals
__device__ float g_P[(size_t)NVARS * DIM];     // variables @ W1
__device__ float g_Q[(size_t)NFACT * DIM];     // factors  @ W2
__device__ float g_aggr[(size_t)NVARS * DIM];  // segment_sum of messages

// ---------------------------------------------------------------------------
// f32x2 helpers (Blackwell packed fp32 pipe — 2x FFMA lane rate)
// ---------------------------------------------------------------------------
__device__ __forceinline__ void ffma2(unsigned long long& acc,
                                      unsigned long long a,
                                      unsigned long long b) {
    asm("fma.rn.f32x2 %0, %1, %2, %0;" : "+l"(acc) : "l"(a), "l"(b));
}
__device__ __forceinline__ unsigned long long pack2(float x) {
    unsigned long long r;
    asm("mov.b64 %0, {%1, %1};" : "=l"(r) : "f"(x));
    return r;
}
__device__ __forceinline__ float2 unpack2(unsigned long long v) {
    float2 r;
    asm("mov.b64 {%0, %1}, %2;" : "=f"(r.x), "=f"(r.y) : "l"(v));
    return r;
}

// ---------------------------------------------------------------------------
// Tiled GEMM: C[M,128] = sum_h A_h[M,128] @ W[h*128 : (h+1)*128, 0:128]
// Optional epilogue: C = resid + relu(acc + bias)
//
// Block: 256 threads = 8 warps, computes 128 rows x 128 cols.
// Warp w: rows [w*16, w*16+16). Lane: cgrp = lane&15 -> cols [cgrp*8, +8),
//         rgrp = lane>>4 -> rows [w*16 + rgrp*8, +8).
// Thread: 8 rows x 8 cols held as 32 f32x2 accumulators (pairs over cols).
// Dynamic smem: sW[128*128] + sA[128*128] = 128 KB.
// ---------------------------------------------------------------------------
__global__ __launch_bounds__(256) void gemm128_kernel(
    const float* __restrict__ A0, const float* __restrict__ A1,
    const float* __restrict__ W, int nhalves,
    const float* __restrict__ bias, const float* __restrict__ resid,
    float* __restrict__ C, int M)
{
    extern __shared__ float smem[];
    float* sW = smem;              // 128*128 floats
    float* sA = smem + 128 * 128;  // 128*128 floats

    const int tid  = threadIdx.x;
    const int lane = tid & 31;
    const int warp = tid >> 5;
    const int cgrp = lane & 15;
    const int rgrp = lane >> 4;
    const int row0 = blockIdx.x * 128;
    const int rows = (M - row0 < 128) ? (M - row0) : 128;
    const int rbase = warp * 16 + rgrp * 8;  // thread's first row within block
    const int c0 = cgrp * 8;                 // thread's first col

    unsigned long long acc[8][4];
#pragma unroll
    for (int r = 0; r < 8; r++)
#pragma unroll
        for (int j = 0; j < 4; j++) acc[r][j] = 0ull;

    for (int h = 0; h < nhalves; h++) {
        const float* Wh = W + (size_t)h * 128 * 128;
        const float* Ah = (h == 0) ? A0 : A1;
        __syncthreads();
        // Stage W half: 4096 float4, coalesced
#pragma unroll 4
        for (int i = tid; i < (128 * 128) / 4; i += 256)
            reinterpret_cast<float4*>(sW)[i] =
                reinterpret_cast<const float4*>(Wh)[i];
        // Stage A tile: rows*32 float4
        const float4* Asrc = reinterpret_cast<const float4*>(Ah + (size_t)row0 * 128);
        for (int i = tid; i < rows * 32; i += 256)
            reinterpret_cast<float4*>(sA)[i] = Asrc[i];
        __syncthreads();

#pragma unroll 4
        for (int k = 0; k < 128; k++) {
            const float* wrow = sW + k * 128 + c0;
            ulonglong2 wA = *reinterpret_cast<const ulonglong2*>(wrow);      // cols c0..c0+3
            ulonglong2 wB = *reinterpret_cast<const ulonglong2*>(wrow + 4);  // cols c0+4..c0+7
            const float* acol = sA + rbase * 128 + k;
#pragma unroll
            for (int r = 0; r < 8; r++) {
                unsigned long long a2 = pack2(acol[r * 128]);
                ffma2(acc[r][0], a2, wA.x);
                ffma2(acc[r][1], a2, wA.y);
                ffma2(acc[r][2], a2, wB.x);
                ffma2(acc[r][3], a2, wB.y);
            }
        }
    }

    // Epilogue
    float bv[8];
    if (bias) {
        float4 b0 = *reinterpret_cast<const float4*>(bias + c0);
        float4 b1 = *reinterpret_cast<const float4*>(bias + c0 + 4);
        bv[0] = b0.x; bv[1] = b0.y; bv[2] = b0.z; bv[3] = b0.w;
        bv[4] = b1.x; bv[5] = b1.y; bv[6] = b1.z; bv[7] = b1.w;
    }
#pragma unroll
    for (int r = 0; r < 8; r++) {
        int row = row0 + rbase + r;
        if (row < M) {
            float o[8];
            float2 u;
            u = unpack2(acc[r][0]); o[0] = u.x; o[1] = u.y;
            u = unpack2(acc[r][1]); o[2] = u.x; o[3] = u.y;
            u = unpack2(acc[r][2]); o[4] = u.x; o[5] = u.y;
            u = unpack2(acc[r][3]); o[6] = u.x; o[7] = u.y;
            if (bias) {
#pragma unroll
                for (int j = 0; j < 8; j++) o[j] = fmaxf(o[j] + bv[j], 0.f);
            }
            if (resid) {
                const float* rp = resid + (size_t)row * 128 + c0;
                float4 r0 = *reinterpret_cast<const float4*>(rp);
                float4 r1 = *reinterpret_cast<const float4*>(rp + 4);
                o[0] += r0.x; o[1] += r0.y; o[2] += r0.z; o[3] += r0.w;
                o[4] += r1.x; o[5] += r1.y; o[6] += r1.z; o[7] += r1.w;
            }
            float* cp = C + (size_t)row * 128 + c0;
            *reinterpret_cast<float4*>(cp)     = make_float4(o[0], o[1], o[2], o[3]);
            *reinterpret_cast<float4*>(cp + 4) = make_float4(o[4], o[5], o[6], o[7]);
        }
    }
}

// ---------------------------------------------------------------------------
// Edge kernel: one warp per edge.
//   m = relu(P[v] + Q[f] + b_msg);  aggr[v] += m  (vectorized L2 reduction)
// ---------------------------------------------------------------------------
__global__ __launch_bounds__(256) void edge_kernel(
    const int* __restrict__ v_to_f, const int* __restrict__ f_to_v,
    const float* __restrict__ bmsg, int E)
{
    const int gwarp = (blockIdx.x * blockDim.x + threadIdx.x) >> 5;
    if (gwarp >= E) return;
    const int lane = threadIdx.x & 31;
    const int v = __ldg(v_to_f + gwarp);
    const int f = __ldg(f_to_v + gwarp);
    const int c = lane * 4;

    float4 p = *reinterpret_cast<const float4*>(g_P + (size_t)v * 128 + c);
    float4 q = *reinterpret_cast<const float4*>(g_Q + (size_t)f * 128 + c);
    float4 b = __ldg(reinterpret_cast<const float4*>(bmsg + c));

    float m0 = fmaxf(p.x + q.x + b.x, 0.f);
    float m1 = fmaxf(p.y + q.y + b.y, 0.f);
    float m2 = fmaxf(p.z + q.z + b.z, 0.f);
    float m3 = fmaxf(p.w + q.w + b.w, 0.f);

    float* dst = g_aggr + (size_t)v * 128 + c;
    asm volatile("red.global.add.v4.f32 [%0], {%1, %2, %3, %4};"
                 :: "l"(dst), "f"(m0), "f"(m1), "f"(m2), "f"(m3)
                 : "memory");
}

// ---------------------------------------------------------------------------
// Launch
// ---------------------------------------------------------------------------
extern "C" void kernel_launch(void* const* d_in, const int* in_sizes, int n_in,
                              void* d_out, int out_size)
{
    const float* variables = (const float*)d_in[0];
    const float* factors   = (const float*)d_in[1];
    const int*   v_to_f    = (const int*)d_in[2];
    const int*   f_to_v    = (const int*)d_in[3];
    // d_in[4] = edge_attr: unused (reference zeroes it)
    const float* W_msg     = (const float*)d_in[5];  // [257,128]
    const float* b_msg     = (const float*)d_in[6];  // [128]
    const float* W_comb    = (const float*)d_in[7];  // [256,128]
    const float* b_comb    = (const float*)d_in[8];  // [128]
    float* out = (float*)d_out;

    const int n_vars = in_sizes[0] / DIM;
    const int n_fact = in_sizes[1] / DIM;
    const int n_edge = in_sizes[2];

    float *pP = nullptr, *pQ = nullptr, *pAggr = nullptr;
    cudaGetSymbolAddress((void**)&pP, g_P);
    cudaGetSymbolAddress((void**)&pQ, g_Q);
    cudaGetSymbolAddress((void**)&pAggr, g_aggr);

    const size_t smem_bytes = (size_t)2 * 128 * 128 * sizeof(float);  // 128 KB
    cudaFuncSetAttribute(gemm128_kernel,
                         cudaFuncAttributeMaxDynamicSharedMemorySize,
                         (int)smem_bytes);

    cudaStream_t s = 0;

    // 1) zero aggregation buffer
    cudaMemsetAsync(pAggr, 0, (size_t)n_vars * DIM * sizeof(float), s);

    // 2) P = variables @ W_msg[0:128]
    gemm128_kernel<<<(n_vars + 127) / 128, 256, smem_bytes, s>>>(
        variables, nullptr, W_msg, 1, nullptr, nullptr, pP, n_vars);

    // 3) Q = factors @ W_msg[128:256]
    gemm128_kernel<<<(n_fact + 127) / 128, 256, smem_bytes, s>>>(
        factors, nullptr, W_msg + 128 * 128, 1, nullptr, nullptr, pQ, n_fact);

    // 4) per-edge relu + scatter-add
    int edge_blocks = (n_edge + 7) / 8;  // 8 warps (edges) per 256-thread block
    edge_kernel<<<edge_blocks, 256, 0, s>>>(v_to_f, f_to_v, b_msg, n_edge);

    // 5) out = variables + relu(variables@Wc1 + aggr@Wc2 + b_comb)
    gemm128_kernel<<<(n_vars + 127) / 128, 256, smem_bytes, s>>>(
        variables, pAggr, W_comb, 2, b_comb, variables, out, n_vars);
}

// round 12
// speedup vs baseline: 1.0011x; 1.0001x over previous
#include <cuda_runtime.h>
#include <cuda_bf16.h>
#include <cstdint>

// Problem shape (fixed for this problem instance)
#define NVARS  100000
#define NFACT  50000
#define NEDGES 1000000
#define DIM    128

// Scratch (no cudaMalloc allowed) — device globals
__device__ float g_P[(size_t)NVARS * DIM];     // variables @ W1
__device__ float g_Q[(size_t)NFACT * DIM];     // factors  @ W2
__device__ float g_aggr[(size_t)NVARS * DIM];  // segment_sum of messages

// ---------------------------------------------------------------------------
// f32x2 helpers (Blackwell packed fp32 pipe — 2x FFMA lane rate)
// ---------------------------------------------------------------------------
__device__ __forceinline__ void ffma2(unsigned long long& acc,
                                      unsigned long long a,
                                      unsigned long long b) {
    asm("fma.rn.f32x2 %0, %1, %2, %0;" : "+l"(acc) : "l"(a), "l"(b));
}
__device__ __forceinline__ unsigned long long pack2(float x) {
    unsigned long long r;
    asm("mov.b64 %0, {%1, %1};" : "=l"(r) : "f"(x));
    return r;
}
__device__ __forceinline__ float2 unpack2(unsigned long long v) {
    float2 r;
    asm("mov.b64 {%0, %1}, %2;" : "=f"(r.x), "=f"(r.y) : "l"(v));
    return r;
}

// ---------------------------------------------------------------------------
// Tiled GEMM: C[M,128] = sum_h A_h[M,128] @ W[h*128 : (h+1)*128, 0:128]
// Optional epilogue: C = resid + relu(acc + bias)
//
// Block: 256 threads = 8 warps, computes 128 rows x 128 cols.
// Warp w: rows [w*16, w*16+16). Lane: cgrp = lane&15 -> cols [cgrp*8, +8),
//         rgrp = lane>>4 -> rows [w*16 + rgrp*8, +8).
// Thread: 8 rows x 8 cols held as 32 f32x2 accumulators (pairs over cols).
// Dynamic smem: sW[128*128] + sA[128*128] = 128 KB.
// ---------------------------------------------------------------------------
__global__ __launch_bounds__(256) void gemm128_kernel(
    const float* __restrict__ A0, const float* __restrict__ A1,
    const float* __restrict__ W, int nhalves,
    const float* __restrict__ bias, const float* __restrict__ resid,
    float* __restrict__ C, int M)
{
    extern __shared__ float smem[];
    float* sW = smem;              // 128*128 floats
    float* sA = smem + 128 * 128;  // 128*128 floats

    const int tid  = threadIdx.x;
    const int lane = tid & 31;
    const int warp = tid >> 5;
    const int cgrp = lane & 15;
    const int rgrp = lane >> 4;
    const int row0 = blockIdx.x * 128;
    const int rows = (M - row0 < 128) ? (M - row0) : 128;
    const int rbase = warp * 16 + rgrp * 8;  // thread's first row within block
    const int c0 = cgrp * 8;                 // thread's first col

    unsigned long long acc[8][4];
#pragma unroll
    for (int r = 0; r < 8; r++)
#pragma unroll
        for (int j = 0; j < 4; j++) acc[r][j] = 0ull;

    for (int h = 0; h < nhalves; h++) {
        const float* Wh = W + (size_t)h * 128 * 128;
        const float* Ah = (h == 0) ? A0 : A1;
        __syncthreads();
        // Stage W half: 4096 float4, coalesced
#pragma unroll 4
        for (int i = tid; i < (128 * 128) / 4; i += 256)
            reinterpret_cast<float4*>(sW)[i] =
                reinterpret_cast<const float4*>(Wh)[i];
        // Stage A tile: rows*32 float4
        const float4* Asrc = reinterpret_cast<const float4*>(Ah + (size_t)row0 * 128);
        for (int i = tid; i < rows * 32; i += 256)
            reinterpret_cast<float4*>(sA)[i] = Asrc[i];
        __syncthreads();

#pragma unroll 4
        for (int k = 0; k < 128; k++) {
            const float* wrow = sW + k * 128 + c0;
            ulonglong2 wA = *reinterpret_cast<const ulonglong2*>(wrow);      // cols c0..c0+3
            ulonglong2 wB = *reinterpret_cast<const ulonglong2*>(wrow + 4);  // cols c0+4..c0+7
            const float* acol = sA + rbase * 128 + k;
#pragma unroll
            for (int r = 0; r < 8; r++) {
                unsigned long long a2 = pack2(acol[r * 128]);
                ffma2(acc[r][0], a2, wA.x);
                ffma2(acc[r][1], a2, wA.y);
                ffma2(acc[r][2], a2, wB.x);
                ffma2(acc[r][3], a2, wB.y);
            }
        }
    }

    // Epilogue
    float bv[8];
    if (bias) {
        float4 b0 = *reinterpret_cast<const float4*>(bias + c0);
        float4 b1 = *reinterpret_cast<const float4*>(bias + c0 + 4);
        bv[0] = b0.x; bv[1] = b0.y; bv[2] = b0.z; bv[3] = b0.w;
        bv[4] = b1.x; bv[5] = b1.y; bv[6] = b1.z; bv[7] = b1.w;
    }
#pragma unroll
    for (int r = 0; r < 8; r++) {
        int row = row0 + rbase + r;
        if (row < M) {
            float o[8];
            float2 u;
            u = unpack2(acc[r][0]); o[0] = u.x; o[1] = u.y;
            u = unpack2(acc[r][1]); o[2] = u.x; o[3] = u.y;
            u = unpack2(acc[r][2]); o[4] = u.x; o[5] = u.y;
            u = unpack2(acc[r][3]); o[6] = u.x; o[7] = u.y;
            if (bias) {
#pragma unroll
                for (int j = 0; j < 8; j++) o[j] = fmaxf(o[j] + bv[j], 0.f);
            }
            if (resid) {
                const float* rp = resid + (size_t)row * 128 + c0;
                float4 r0 = *reinterpret_cast<const float4*>(rp);
                float4 r1 = *reinterpret_cast<const float4*>(rp + 4);
                o[0] += r0.x; o[1] += r0.y; o[2] += r0.z; o[3] += r0.w;
                o[4] += r1.x; o[5] += r1.y; o[6] += r1.z; o[7] += r1.w;
            }
            float* cp = C + (size_t)row * 128 + c0;
            *reinterpret_cast<float4*>(cp)     = make_float4(o[0], o[1], o[2], o[3]);
            *reinterpret_cast<float4*>(cp + 4) = make_float4(o[4], o[5], o[6], o[7]);
        }
    }
}

// ---------------------------------------------------------------------------
// Edge kernel: one warp per edge.
//   m = relu(P[v] + Q[f] + b_msg);  aggr[v] += m  (vectorized L2 reduction)
// ---------------------------------------------------------------------------
__global__ __launch_bounds__(256) void edge_kernel(
    const int* __restrict__ v_to_f, const int* __restrict__ f_to_v,
    const float* __restrict__ bmsg, int E)
{
    const int gwarp = (blockIdx.x * blockDim.x + threadIdx.x) >> 5;
    if (gwarp >= E) return;
    const int lane = threadIdx.x & 31;
    const int v = __ldg(v_to_f + gwarp);
    const int f = __ldg(f_to_v + gwarp);
    const int c = lane * 4;

    float4 p = *reinterpret_cast<const float4*>(g_P + (size_t)v * 128 + c);
    float4 q = *reinterpret_cast<const float4*>(g_Q + (size_t)f * 128 + c);
    float4 b = __ldg(reinterpret_cast<const float4*>(bmsg + c));

    float m0 = fmaxf(p.x + q.x + b.x, 0.f);
    float m1 = fmaxf(p.y + q.y + b.y, 0.f);
    float m2 = fmaxf(p.z + q.z + b.z, 0.f);
    float m3 = fmaxf(p.w + q.w + b.w, 0.f);

    float* dst = g_aggr + (size_t)v * 128 + c;
    asm volatile("red.global.add.v4.f32 [%0], {%1, %2, %3, %4};"
                 :: "l"(dst), "f"(m0), "f"(m1), "f"(m2), "f"(m3)
                 : "memory");
}

// ---------------------------------------------------------------------------
// Launch
// ---------------------------------------------------------------------------
extern "C" void kernel_launch(void* const* d_in, const int* in_sizes, int n_in,
                              void* d_out, int out_size)
{
    const float* variables = (const float*)d_in[0];
    const float* factors   = (const float*)d_in[1];
    const int*   v_to_f    = (const int*)d_in[2];
    const int*   f_to_v    = (const int*)d_in[3];
    // d_in[4] = edge_attr: unused (reference zeroes it)
    const float* W_msg     = (const float*)d_in[5];  // [257,128]
    const float* b_msg     = (const float*)d_in[6];  // [128]
    const float* W_comb    = (const float*)d_in[7];  // [256,128]
    const float* b_comb    = (const float*)d_in[8];  // [128]
    float* out = (float*)d_out;

    const int n_vars = in_sizes[0] / DIM;
    const int n_fact = in_sizes[1] / DIM;
    const int n_edge = in_sizes[2];

    float *pP = nullptr, *pQ = nullptr, *pAggr = nullptr;
    cudaGetSymbolAddress((void**)&pP, g_P);
    cudaGetSymbolAddress((void**)&pQ, g_Q);
    cudaGetSymbolAddress((void**)&pAggr, g_aggr);

    const size_t smem_bytes = (size_t)2 * 128 * 128 * sizeof(float);  // 128 KB
    cudaFuncSetAttribute(gemm128_kernel,
                         cudaFuncAttributeMaxDynamicSharedMemorySize,
                         (int)smem_bytes);

    cudaStream_t s = 0;

    // 1) zero aggregation buffer
    cudaMemsetAsync(pAggr, 0, (size_t)n_vars * DIM * sizeof(float), s);

    // 2) P = variables @ W_msg[0:128]
    gemm128_kernel<<<(n_vars + 127) / 128, 256, smem_bytes, s>>>(
        variables, nullptr, W_msg, 1, nullptr, nullptr, pP, n_vars);

    // 3) Q = factors @ W_msg[128:256]
    gemm128_kernel<<<(n_fact + 127) / 128, 256, smem_bytes, s>>>(
        factors, nullptr, W_msg + 128 * 128, 1, nullptr, nullptr, pQ, n_fact);

    // 4) per-edge relu + scatter-add
    int edge_blocks = (n_edge + 7) / 8;  // 8 warps (edges) per 256-thread block
    edge_kernel<<<edge_blocks, 256, 0, s>>>(v_to_f, f_to_v, b_msg, n_edge);

    // 5) out = variables + relu(variables@Wc1 + aggr@Wc2 + b_comb)
    gemm128_kernel<<<(n_vars + 127) / 128, 256, smem_bytes, s>>>(
        variables, pAggr, W_comb, 2, b_comb, variables, out, n_vars);
}